// round 9
// baseline (speedup 1.0000x reference)
#include <cuda_runtime.h>
#include <math.h>
#include <stdint.h>

#define IMG_SIZE 255.0f
#define MAXB 64
#define MAXA 65536
#define CAP   65536
#define CHUNK 8192          // keys per block, resident in smem

// ---------------- device scratch (zeroed at load; final block re-zeroes) ----------
__device__ unsigned g_cand[MAXB][CAP];            // boundary-bin candidates
__device__ int      g_hist [MAXB][256];           // byte-3 histogram
__device__ int      g_hist2[MAXB][256];           // byte-2 histogram of candidates
__device__ int      g_rowpos[MAXB];
__device__ int      g_ncand[MAXB];
__device__ int      g_ticket[MAXB];               // phase-A completion per row
__device__ int      g_ticket2[MAXB];              // phase-D completion per row
__device__ int      g_rowdone;
// floats: 0 loss_loc_sum, 1 pos_nll_sum, 2 pos_err_sum, 3 size_x, 4 size_y, 5 neg_nll_sel
__device__ float    g_f[8];
// ints:   0 N, 1 pos_correct, 2 neg_selected_total, 3 neg_correct
__device__ int      g_i[4];

__device__ __forceinline__ float smooth_l1(float x) {
    float ax = fabsf(x);
    return (ax < 1.0f) ? 0.5f * x * x : ax - 0.5f;
}
__device__ __forceinline__ float softplus(float d) {   // nll at target 0
    return fmaxf(d, 0.0f) + log1pf(expf(-fabsf(d)));
}
__device__ __forceinline__ unsigned f2ord(float f) {
    unsigned u = __float_as_uint(f);
    return (u & 0x80000000u) ? ~u : (u | 0x80000000u);
}
__device__ __forceinline__ float ord2f(unsigned k) {
    unsigned u = (k & 0x80000000u) ? (k & 0x7FFFFFFFu) : ~k;
    return __uint_as_float(u);
}

__device__ __forceinline__ unsigned make_key(float4 g, float areaA, float4 pr,
                                             float d, bool* pos) {
    float ax0 = pr.x - pr.z * 0.5f, ay0 = pr.y - pr.w * 0.5f;
    float ax1 = pr.x + pr.z * 0.5f, ay1 = pr.y + pr.w * 0.5f;
    float iw = fmaxf(fminf(g.z, ax1) - fmaxf(g.x, ax0), 0.0f);
    float ih = fmaxf(fminf(g.w, ay1) - fmaxf(g.y, ay0), 0.0f);
    float inter = iw * ih;
    float iou = inter / (areaA + (ax1 - ax0) * (ay1 - ay0) - inter);
    *pos = (iou >= 0.6f);
    return (iou <= 0.3f) ? f2ord(d) : 0u;
}

__device__ __noinline__ void pos_work(const float* __restrict__ loc,
                                      float4 g, float4 pr, float d,
                                      size_t idx, int b) {
    atomicAdd(&g_rowpos[b], 1);
    atomicAdd(&g_i[0], 1);
    atomicAdd(&g_f[1], softplus(-d));
    if (d > 0.0f) atomicAdd(&g_i[1], 1);
    const float* lp = loc + idx * 4;
    float l0 = lp[0], l1 = lp[1], l2 = lp[2], l3 = lp[3];
    float gw = g.z - g.x, gh = g.w - g.y;
    float gcx = (g.x + g.z) * 0.5f, gcy = (g.y + g.w) * 0.5f;
    float e0 = (gcx - pr.x) / (0.1f * pr.z);
    float e1 = (gcy - pr.y) / (0.1f * pr.w);
    float e2 = logf(gw / pr.z) / 0.2f;
    float e3 = logf(gh / pr.w) / 0.2f;
    atomicAdd(&g_f[0], smooth_l1(l0 - e0) + smooth_l1(l1 - e1) +
                       smooth_l1(l2 - e2) + smooth_l1(l3 - e3));
    float dcx = pr.x + l0 * 0.1f * pr.z;
    float dcy = pr.y + l1 * 0.1f * pr.w;
    float dw  = pr.z * expf(l2 * 0.2f);
    float dh  = pr.w * expf(l3 * 0.2f);
    float dx0 = dcx - dw * 0.5f, dy0 = dcy - dh * 0.5f;
    float ex = (g.x - dx0) * IMG_SIZE, ey = (g.y - dy0) * IMG_SIZE;
    atomicAdd(&g_f[2], sqrtf(ex * ex + ey * ey));
    atomicAdd(&g_f[3], fabsf(g.z - (dx0 + dw)));
    atomicAdd(&g_f[4], fabsf(g.w - (dy0 + dh)));
}

// parallel cutoff over 256-bin histogram in shared s (destroyed); blockDim=256
__device__ __forceinline__ void suffix_cutoff(int* s, int k, int* out_c, int* out_kk) {
    int t = threadIdx.x;
    #pragma unroll
    for (int off = 1; off < 256; off <<= 1) {
        int add = (t + off < 256) ? s[t + off] : 0;
        __syncthreads();
        s[t] += add;
        __syncthreads();
    }
    __shared__ int sc, skk;
    if (t == 0) { sc = 0; skk = k; }
    __syncthreads();
    int St = s[t];
    int Sn = (t < 255) ? s[t + 1] : 0;
    if (Sn < k && k <= St) { sc = t; skk = k - Sn; }
    __syncthreads();
    *out_c = sc; *out_kk = skk;
}

__device__ __forceinline__ void warp_hist_add(int* sh, unsigned bin) {
    unsigned m = __match_any_sync(0xffffffffu, bin);
    if ((threadIdx.x & 31) == (unsigned)(__ffs(m) - 1)) atomicAdd(&sh[bin], __popc(m));
}

// =============== the single kernel ===============
__global__ void __launch_bounds__(256, 4) k_all(
        const float*  __restrict__ loc,
        const float4* __restrict__ conf4,
        const float4* __restrict__ gt4,
        const float4* __restrict__ anch,
        float* __restrict__ out, int out_size,
        int A, int B) {
    int b = blockIdx.y;
    int t = threadIdx.x;
    int bpr = gridDim.x;
    size_t rowoff = (size_t)b * A;
    __shared__ unsigned sk[CHUNK];      // 32 KB block-resident keys
    __shared__ int sh[256];
    __shared__ int sh2[256];
    __shared__ float s_sum;
    __shared__ int s_corr, s_cnt, s_w, s_base, s_last, s_fin;

    float4 g = gt4[b];
    float areaA = (g.z - g.x) * (g.w - g.y);
    int base = blockIdx.x * CHUNK;

    // ---- Phase A: keys -> smem, byte-3 histogram, sparse positive work ----
    sh[t] = 0;
    __syncthreads();
    #pragma unroll 4
    for (int it = 0; it < CHUNK / 512; ++it) {        // 16 iters, 2 elems/thread
        int i2 = it * 256 + t;
        int a0 = base + i2 * 2;
        float4 cA = conf4[(rowoff + (size_t)a0) >> 1];
        float4 p0 = anch[a0], p1 = anch[a0 + 1];
        float d0 = cA.y - cA.x, d1 = cA.w - cA.z;
        bool q0, q1;
        unsigned k0 = make_key(g, areaA, p0, d0, &q0);
        unsigned k1 = make_key(g, areaA, p1, d1, &q1);
        sk[i2 * 2] = k0; sk[i2 * 2 + 1] = k1;
        warp_hist_add(sh, k0 >> 24);
        warp_hist_add(sh, k1 >> 24);
        if (q0) pos_work(loc, g, p0, d0, rowoff + a0, b);
        if (q1) pos_work(loc, g, p1, d1, rowoff + a0 + 1, b);
    }
    __syncthreads();
    if (sh[t]) atomicAdd(&g_hist[b][t], sh[t]);
    __threadfence();
    __syncthreads();
    if (t == 0) atomicAdd(&g_ticket[b], 1);

    // ---- Phase B: wait for this row's histogram (all CTAs resident: 512 <= 592) ----
    if (t == 0) {
        volatile int* vt = (volatile int*)g_ticket;
        while (vt[b] != bpr) __nanosleep(64);
    }
    __syncthreads();
    __threadfence();

    // ---- Phase C: row cutoff (byte 3) ----
    int np = __ldcg(&g_rowpos[b]);
    int k = 3 * np; if (k < 10) k = 10; if (k > A - 1) k = A - 1;
    sh[t] = __ldcg(&g_hist[b][t]);
    __syncthreads();
    int c1, kk1;
    suffix_cutoff(sh, k, &c1, &kk1);
    unsigned c1u = (unsigned)c1;

    // ---- Phase D1: scan own smem keys: sums, candidate count, byte-2 hist ----
    sh2[t] = 0;
    if (t == 0) { s_sum = 0.0f; s_corr = 0; s_cnt = 0; s_w = 0; }
    __syncthreads();
    float lsum = 0.0f; int lcorr = 0, lcnt = 0;
    #pragma unroll 4
    for (int i = t; i < CHUNK; i += 256) {
        unsigned u = sk[i];
        unsigned bin = u >> 24;
        if (bin > c1u) {
            lsum += softplus(ord2f(u));
            if (u <= 0x80000000u) lcorr++;             // d <= 0 -> pred==0
        } else if (bin == c1u) {
            lcnt++;
            unsigned am = __activemask();
            unsigned b2 = (u >> 16) & 0xFFu;
            unsigned m2 = __match_any_sync(am, b2);
            if ((unsigned)(t & 31) == (unsigned)(__ffs(m2) - 1))
                atomicAdd(&sh2[b2], __popc(m2));
        }
    }
    #pragma unroll
    for (int o = 16; o > 0; o >>= 1) {
        lsum  += __shfl_down_sync(0xffffffffu, lsum, o);
        lcorr += __shfl_down_sync(0xffffffffu, lcorr, o);
        lcnt  += __shfl_down_sync(0xffffffffu, lcnt, o);
    }
    if ((t & 31) == 0) {
        atomicAdd(&s_sum, lsum); atomicAdd(&s_corr, lcorr); atomicAdd(&s_cnt, lcnt);
    }
    __syncthreads();
    int bn = s_cnt;
    if (t == 0) {
        s_base = bn ? atomicAdd(&g_ncand[b], bn) : 0;  // one global atomic per block
        if (s_sum != 0.0f) atomicAdd(&g_f[5], s_sum);
        if (s_corr)        atomicAdd(&g_i[3], s_corr);
    }
    if (sh2[t]) atomicAdd(&g_hist2[b][t], sh2[t]);
    __syncthreads();

    // ---- Phase D2: compact-write candidates to global ----
    int gb = s_base;
    for (int i = t; i < CHUNK; i += 256) {
        unsigned u = sk[i];
        bool isC = ((u >> 24) == c1u);
        unsigned m = __ballot_sync(0xffffffffu, isC);
        if (m) {
            int lane = t & 31;
            int wb = 0;
            if (lane == (__ffs(m) - 1)) wb = atomicAdd(&s_w, __popc(m));
            wb = __shfl_sync(0xffffffffu, wb, __ffs(m) - 1);
            if (isC) g_cand[b][gb + wb + __popc(m & ((1u << lane) - 1))] = u;
        }
    }
    __threadfence();
    __syncthreads();
    if (t == 0) s_last = (atomicAdd(&g_ticket2[b], 1) == bpr - 1);
    __syncthreads();
    if (!s_last) return;

    // ---- Phase E: last block of row drills bytes 2/1/0 ----
    __threadfence();
    int n = __ldcg(&g_ncand[b]); if (n > CAP) n = CAP;

    sh[t] = __ldcg(&g_hist2[b][t]);
    __syncthreads();
    int c2, kk2;
    suffix_cutoff(sh, kk1, &c2, &kk2);

    if (t == 0) { s_sum = 0.0f; s_corr = 0; s_w = 0; }
    __syncthreads();
    float rsum = 0.0f; int rcorr = 0;
    for (int i = t; i < n; i += 256) {
        unsigned u = __ldcg(&g_cand[b][i]);
        unsigned b2 = (u >> 16) & 0xFFu;
        if (b2 > (unsigned)c2) {
            rsum += softplus(ord2f(u));
            if (u <= 0x80000000u) rcorr++;
        } else if (b2 == (unsigned)c2) {
            int p = atomicAdd(&s_w, 1);
            if (p < CHUNK) sk[p] = u;                  // reuse key buffer as stage
        }
    }
    #pragma unroll
    for (int o = 16; o > 0; o >>= 1) {
        rsum  += __shfl_down_sync(0xffffffffu, rsum, o);
        rcorr += __shfl_down_sync(0xffffffffu, rcorr, o);
    }
    if ((t & 31) == 0) { atomicAdd(&s_sum, rsum); atomicAdd(&s_corr, rcorr); }
    __syncthreads();
    int m2n = s_w;
    bool in_smem = (m2n <= CHUNK);
    int msub = in_smem ? m2n : 0;

    // byte 1 cutoff
    sh[t] = 0;
    __syncthreads();
    if (in_smem) {
        for (int i = t; i < msub; i += 256)
            atomicAdd(&sh[(sk[i] >> 8) & 0xFFu], 1);
    } else {
        for (int i = t; i < n; i += 256) {
            unsigned u = __ldcg(&g_cand[b][i]);
            if (((u >> 16) & 0xFFu) == (unsigned)c2)
                atomicAdd(&sh[(u >> 8) & 0xFFu], 1);
        }
    }
    __syncthreads();
    int c3, kk3;
    suffix_cutoff(sh, kk2, &c3, &kk3);

    // byte 0 cutoff
    sh[t] = 0;
    __syncthreads();
    if (in_smem) {
        for (int i = t; i < msub; i += 256) {
            unsigned u = sk[i];
            if (((u >> 8) & 0xFFu) == (unsigned)c3) atomicAdd(&sh[u & 0xFFu], 1);
        }
    } else {
        for (int i = t; i < n; i += 256) {
            unsigned u = __ldcg(&g_cand[b][i]);
            if (((u >> 16) & 0xFFu) == (unsigned)c2 && ((u >> 8) & 0xFFu) == (unsigned)c3)
                atomicAdd(&sh[u & 0xFFu], 1);
        }
    }
    __syncthreads();
    int c4, kkf;
    suffix_cutoff(sh, kk3, &c4, &kkf);

    unsigned v = (c1u << 24) | ((unsigned)c2 << 16) | ((unsigned)c3 << 8) | (unsigned)c4;
    unsigned vlow = v & 0xFFFFu;

    float fsum = 0.0f; int fcorr = 0;
    if (in_smem) {
        for (int i = t; i < msub; i += 256) {
            unsigned u = sk[i];
            if ((u & 0xFFFFu) > vlow) {
                fsum += softplus(ord2f(u));
                if (u <= 0x80000000u) fcorr++;
            }
        }
    } else {
        for (int i = t; i < n; i += 256) {
            unsigned u = __ldcg(&g_cand[b][i]);
            if (u > v && ((u >> 16) & 0xFFu) == (unsigned)c2) {
                fsum += softplus(ord2f(u));
                if (u <= 0x80000000u) fcorr++;
            }
        }
    }
    #pragma unroll
    for (int o = 16; o > 0; o >>= 1) {
        fsum  += __shfl_down_sync(0xffffffffu, fsum, o);
        fcorr += __shfl_down_sync(0xffffffffu, fcorr, o);
    }
    if ((t & 31) == 0) { atomicAdd(&s_sum, fsum); atomicAdd(&s_corr, fcorr); }
    __syncthreads();
    if (t == 0) {
        float dv = ord2f(v);
        float tie_nll = (kkf > 0) ? (float)kkf * softplus(dv) : 0.0f;
        int   tie_cor = (kkf > 0 && v <= 0x80000000u) ? kkf : 0;
        atomicAdd(&g_f[5], s_sum + tie_nll);
        atomicAdd(&g_i[3], s_corr + tie_cor);
        atomicAdd(&g_i[2], k);
        __threadfence();
        s_fin = (atomicAdd(&g_rowdone, 1) == B - 1);
    }
    __syncthreads();
    if (!s_fin) return;

    // ---- Phase F: globally last block finalizes + resets scratch ----
    __threadfence();
    if (t == 0) {
        float Nf0 = (float)__ldcg(&g_i[0]);
        float Nf = fmaxf(Nf0, 1.0f);
        float loss_loc = __ldcg(&g_f[0]) / (Nf * 4.0f);
        float wsum = Nf0 + (float)__ldcg(&g_i[2]) * (1.0f / 3.0f);
        float loss_cls = (__ldcg(&g_f[1]) + __ldcg(&g_f[5]) * (1.0f / 3.0f)) / wsum;
        float pos_acc = (float)__ldcg(&g_i[1]) / fmaxf((float)__ldcg(&g_i[0]), 1.0f);
        float neg_acc = (float)__ldcg(&g_i[3]) / fmaxf((float)__ldcg(&g_i[2]), 1.0f);
        float vals[8] = {loss_loc, loss_cls, pos_acc, neg_acc,
                         __ldcg(&g_f[2]) / Nf,
                         __ldcg(&g_f[3]) / Nf * IMG_SIZE,
                         __ldcg(&g_f[4]) / Nf * IMG_SIZE, Nf0};
        for (int i = 0; i < 8 && i < out_size; i++) out[i] = vals[i];
    }
    for (int i = t; i < MAXB * 256; i += 256) {
        ((int*)g_hist)[i] = 0;
        ((int*)g_hist2)[i] = 0;
    }
    if (t < MAXB) {
        g_rowpos[t] = 0; g_ncand[t] = 0; g_ticket[t] = 0; g_ticket2[t] = 0;
    }
    if (t < 8) g_f[t] = 0.0f;
    if (t < 4) g_i[t] = 0;
    if (t == 0) g_rowdone = 0;
}

// ---------------- launch ----------------
extern "C" void kernel_launch(void* const* d_in, const int* in_sizes, int n_in,
                              void* d_out, int out_size) {
    const float*  loc     = (const float*)d_in[0];
    const float4* conf4   = (const float4*)d_in[1];
    const float4* gt      = (const float4*)d_in[2];
    const float4* anchors = (const float4*)d_in[3];
    int B = in_sizes[2] / 4;
    int A = in_sizes[3] / 4;
    if (B > MAXB) B = MAXB;
    if (A > MAXA) A = MAXA;

    int bpr = (A + CHUNK - 1) / CHUNK;   // 8 for A=65536 -> 512 blocks, all resident
    k_all<<<dim3(bpr, B), 256>>>(loc, conf4, gt, anchors,
                                 (float*)d_out, out_size, A, B);
}